// round 10
// baseline (speedup 1.0000x reference)
#include <cuda_runtime.h>

#define NP     8192
#define NQ     32768
#define CH     64
#define G      64
#define NCELL  (G * G)
#define HCELL  (1.0f / 64.0f)   // exact power of two
#define EPS    1e-5f            // pruning margin >> fp formula error (~2e-6)

#define T_TILES 512             // 32x32 transpose tiles: (64/32)*(8192/32)
#define L      8                // lanes cooperating per query
#define HB     (NQ / 256)       // hist blocks in k_pre

typedef unsigned long long u64;
#define KPAD 0xFF8000007FFFFFFFULL   // key(+INF, id=0x7fffffff)

// ---- scratch (__device__ globals: allocation-free rule) ----
// Counters start zero (static init) and are re-zeroed by k_gather each call.
__device__ int    g_cnt[NCELL],  g_off[NCELL + 1];    // points
__device__ int    g_qcnt[NCELL], g_qoff[NCELL + 1];   // queries
__device__ unsigned g_done;      // k_pre tail-block counter (self-resetting)
__device__ int    g_pkey[NP];    // packed cell<<16 | rank  (points)
__device__ int    g_qkey[NQ];    // packed cell<<16 | rank  (queries)
__device__ float4 g_pts[NP];     // cell-sorted points : (x, y, |c|^2, orig-id)
__device__ float4 g_q[NQ];       // cell-sorted queries: (qx, qy, |q|^2, qid)
__device__ int4   g_nn[NQ];      // per ORIGINAL qid: 4 neighbor ORIG ids
__device__ float  g_vt[NP * CH]; // values transposed: vt[orig][c]

static __device__ __forceinline__ int cell_clamped(float px, float py) {
    int cx = (int)(px * (float)G); cx = cx < 0 ? 0 : (cx > G - 1 ? G - 1 : cx);
    int cy = (int)(py * (float)G); cy = cy < 0 ? 0 : (cy > G - 1 ? G - 1 : cy);
    return cy * G + cx;
}

// monotonic (total-order) float -> u32 encode; strict order preserved
static __device__ __forceinline__ unsigned fenc(float d) {
    unsigned u = __float_as_uint(d);
    return u ^ (((unsigned)((int)u >> 31)) | 0x80000000u);
}
// threshold key with id = 0: key < tkey(thr)  <=>  d < thr (strict)
static __device__ __forceinline__ u64 tkey(float thr) {
    return ((u64)fenc(thr)) << 32;
}

// ---------------------------------------------------------------------------
// K1: histogram-with-rank; LAST block also runs the dual scan
// (threadfence + done-counter tail-block pattern, counter self-resets).
// ---------------------------------------------------------------------------
__global__ void __launch_bounds__(256) k_pre(
    const float2* __restrict__ coords,
    const float2* __restrict__ newc,
    const float*  __restrict__ shift)
{
    int i = blockIdx.x * 256 + threadIdx.x;   // 0..NQ-1
    float sx = shift[0], sy = shift[1];
    float2 a = (i < NP) ? coords[i] : newc[i - NP];
    float qx = __fsub_rn(a.x, sx), qy = __fsub_rn(a.y, sy);
    int qc = cell_clamped(qx, qy);
    int qr = atomicAdd(&g_qcnt[qc], 1);
    g_qkey[i] = (qc << 16) | qr;
    if (i < NP) {
        int pc = cell_clamped(a.x, a.y);
        int pr = atomicAdd(&g_cnt[pc], 1);
        g_pkey[i] = (pc << 16) | pr;
    }

    __threadfence();
    __shared__ bool isLast;
    if (threadIdx.x == 0)
        isLast = (atomicAdd(&g_done, 1u) == HB - 1);
    __syncthreads();
    if (!isLast) return;
    if (threadIdx.x == 0) g_done = 0;          // reset for next replay

    // ---- dual exclusive scan of both 4096-cell histograms ----
    __shared__ int pp[256], pq[256];
    int t = threadIdx.x, base = t * 16;
    int lp[16], lq[16], sp = 0, sq = 0;
    #pragma unroll
    for (int k = 0; k < 16; k++) {
        lp[k] = sp; sp += g_cnt[base + k];
        lq[k] = sq; sq += g_qcnt[base + k];
    }
    pp[t] = sp; pq[t] = sq;
    __syncthreads();
    for (int o = 1; o < 256; o <<= 1) {
        int vp = (t >= o) ? pp[t - o] : 0;
        int vq = (t >= o) ? pq[t - o] : 0;
        __syncthreads();
        pp[t] += vp; pq[t] += vq;
        __syncthreads();
    }
    int prep = (t == 0) ? 0 : pp[t - 1];
    int preq = (t == 0) ? 0 : pq[t - 1];
    #pragma unroll
    for (int k = 0; k < 16; k++) {
        g_off[base + k]  = prep + lp[k];
        g_qoff[base + k] = preq + lq[k];
    }
    if (t == 255) { g_off[NCELL] = NP; g_qoff[NCELL] = NQ; }
}

// ---------------------------------------------------------------------------
// K2: atomic-free scatter (blocks [0,HB)) + values-transpose (rest).
// ---------------------------------------------------------------------------
__global__ void __launch_bounds__(256) k_scatter(
    const float*  __restrict__ values,
    const float2* __restrict__ coords,
    const float2* __restrict__ newc,
    const float*  __restrict__ shift)
{
    if (blockIdx.x >= HB) {
        __shared__ float s[32][33];
        int tb = blockIdx.x - HB;
        int tc = tb & 1;
        int to = tb >> 1;
        int tx = threadIdx.x & 31, ty = threadIdx.x >> 5;
        #pragma unroll
        for (int d = 0; d < 4; d++) {
            int cl = ty + d * 8;
            s[cl][tx] = values[(tc * 32 + cl) * NP + to * 32 + tx];
        }
        __syncthreads();
        #pragma unroll
        for (int d = 0; d < 4; d++) {
            int ol = ty + d * 8;
            g_vt[(to * 32 + ol) * CH + tc * 32 + tx] = s[tx][ol];
        }
        return;
    }
    int i = blockIdx.x * 256 + threadIdx.x;
    float sx = shift[0], sy = shift[1];
    float2 a = (i < NP) ? coords[i] : newc[i - NP];
    float qx = __fsub_rn(a.x, sx), qy = __fsub_rn(a.y, sy);
    float sq = __fadd_rn(__fmul_rn(qx, qx), __fmul_rn(qy, qy));
    int qk = g_qkey[i];
    g_q[g_qoff[qk >> 16] + (qk & 0xffff)] =
        make_float4(qx, qy, sq, __int_as_float(i));
    if (i < NP) {
        int pk = g_pkey[i];
        float c2 = __fadd_rn(__fmul_rn(a.x, a.x), __fmul_rn(a.y, a.y));
        g_pts[g_off[pk >> 16] + (pk & 0xffff)] =
            make_float4(a.x, a.y, c2, __int_as_float(i));
    }
}

// ---------------------------------------------------------------------------
// K3: exact 4-NN, 8 lanes/query, adaptive sweep (3x3 -> ring2 -> safety
// rings). d computed with the verified fp32 formula, then (d, orig_id)
// packed into ONE sortable u64 key (monotonic encode) so every insertion
// level is a single u64 compare. Ordering identical to the float
// lexicographic path (+-0.0 distance excepted, measure-zero).
// ---------------------------------------------------------------------------
__global__ void __launch_bounds__(256) k_query()
{
    const int gt   = blockIdx.x * 256 + threadIdx.x;
    const int grp  = gt >> 3;          // query index (sorted order)
    const int lane = gt & 7;

    float4 q = g_q[grp];
    const float qx = q.x, qy = q.y, sq = q.z;
    const int qid = __float_as_int(q.w);
    const int cx = (int)floorf(qx * (float)G);   // may be -1 near lower edge
    const int cy = (int)floorf(qy * (float)G);

    u64 k0 = KPAD, k1 = KPAD, k2 = KPAD, k3 = KPAD;

#define PAIR(n) {                                                        \
    float4 p = g_pts[n];                                                 \
    float qc = __fmaf_rn(qy, p.y, __fmul_rn(qx, p.x));                   \
    float tt = __fadd_rn(sq, p.z);                                       \
    float d  = __fmaf_rn(-2.0f, qc, tt);                                 \
    u64 kk = (((u64)fenc(d)) << 32) | (unsigned)__float_as_int(p.w);     \
    if (kk < k3) {                                                       \
        if (kk < k2) {                                                   \
            k3 = k2;                                                     \
            if (kk < k1) {                                               \
                k2 = k1;                                                 \
                if (kk < k0) { k1 = k0; k0 = kk; } else k1 = kk;         \
            } else k2 = kk;                                              \
        } else k3 = kk;                                                  \
    } }

#define RUN(s_, e_) { for (int n = (s_) + lane; n < (e_); n += L) PAIR(n) }

#define MERGE(R0, R1, R2, R3, B3K) {                                    \
    int h = 0;                                                          \
    _Pragma("unroll")                                                   \
    for (int k = 0; k < 4; k++) {                                       \
        u64 ck = (h == 0) ? k0 : (h == 1) ? k1 : (h == 2) ? k2          \
               : (h == 3) ? k3 : KPAD;                                  \
        u64 mk = ck;                                                    \
        _Pragma("unroll")                                               \
        for (int s = 1; s < L; s <<= 1) {                               \
            u64 ok = __shfl_xor_sync(0xffffffffu, mk, s, L);            \
            if (ok < mk) mk = ok;                                       \
        }                                                               \
        if (k == 0) R0 = (int)(mk & 0xffffffffull);                     \
        else if (k == 1) R1 = (int)(mk & 0xffffffffull);                \
        else if (k == 2) R2 = (int)(mk & 0xffffffffull);                \
        else { R3 = (int)(mk & 0xffffffffull); B3K = mk; }              \
        if (ck == mk) h++;                                              \
    } }

#define BOXBOUND(e_, bv_) {                                              \
    float x0 = (float)(cx - (e_)) * HCELL, y0 = (float)(cy - (e_)) * HCELL; \
    float x1 = (float)(cx + (e_) + 1) * HCELL, y1 = (float)(cy + (e_) + 1) * HCELL; \
    bv_ = fminf(fminf(qx - x0, x1 - qx), fminf(qy - y0, y1 - qy)); }

    // ---- phase 1: 3x3 sweep (row-contiguous) ----
    {
        int iy0 = cy - 1 < 0 ? 0 : cy - 1;
        int iy1 = cy + 1 > G - 1 ? G - 1 : cy + 1;
        int ix0 = cx - 1 < 0 ? 0 : cx - 1;
        int ix1 = cx + 1 > G - 1 ? G - 1 : cx + 1;
        for (int iy = iy0; iy <= iy1; iy++)
            RUN(g_off[iy * G + ix0], g_off[iy * G + ix1 + 1])
    }
    int res0, res1, res2, res3;
    u64 mb3k;
    MERGE(res0, res1, res2, res3, mb3k)

    float bb; BOXBOUND(1, bb)
    bool done = (mb3k < tkey(__fmaf_rn(bb, bb, -EPS)));

    if (!__all_sync(0xffffffffu, done)) {
        // ---- phase 2: ring r=2 (guarded per group; no shfl inside) ----
        if (!done) {
            int ix0 = cx - 2 < 0 ? 0 : cx - 2;
            int ix1 = cx + 2 > G - 1 ? G - 1 : cx + 2;
            if (cy - 2 >= 0)
                RUN(g_off[(cy - 2) * G + ix0], g_off[(cy - 2) * G + ix1 + 1])
            if (cy + 2 <= G - 1)
                RUN(g_off[(cy + 2) * G + ix0], g_off[(cy + 2) * G + ix1 + 1])
            int iy0 = cy - 1 < 0 ? 0 : cy - 1;
            int iy1 = cy + 1 > G - 1 ? G - 1 : cy + 1;
            for (int iy = iy0; iy <= iy1; iy++) {
                if (cx - 2 >= 0) {
                    int c = iy * G + cx - 2;
                    RUN(g_off[c], g_off[c + 1])
                }
                if (cx + 2 <= G - 1) {
                    int c = iy * G + cx + 2;
                    RUN(g_off[c], g_off[c + 1])
                }
            }
        }
        MERGE(res0, res1, res2, res3, mb3k)   // uniform re-merge (safe for done)
        BOXBOUND(2, bb)
        done = done || (mb3k < tkey(__fmaf_rn(bb, bb, -EPS)));

        if (!__all_sync(0xffffffffu, done)) {
            // ---- phase 3: safety rings r>=3 ----
            for (int r = 3; r < 96; r++) {
                if (__all_sync(0xffffffffu, done)) break;
                if (!done) {
                    int ylo = cy - r, yhi = cy + r, xlo = cx - r, xhi = cx + r;
                    int ix0 = xlo < 0 ? 0 : xlo;
                    int ix1 = xhi > G - 1 ? G - 1 : xhi;
                    if (ylo >= 0)
                        RUN(g_off[ylo * G + ix0], g_off[ylo * G + ix1 + 1])
                    if (yhi <= G - 1)
                        RUN(g_off[yhi * G + ix0], g_off[yhi * G + ix1 + 1])
                    int iy0 = ylo + 1 < 0 ? 0 : ylo + 1;
                    int iy1 = yhi - 1 > G - 1 ? G - 1 : yhi - 1;
                    for (int iy = iy0; iy <= iy1; iy++) {
                        if (xlo >= 0) {
                            int c = iy * G + xlo;
                            RUN(g_off[c], g_off[c + 1])
                        }
                        if (xhi <= G - 1) {
                            int c = iy * G + xhi;
                            RUN(g_off[c], g_off[c + 1])
                        }
                    }
                }
                u64 nk = k3;   // conservative: min over lanes of lane 4th key
                #pragma unroll
                for (int s = 1; s < L; s <<= 1) {
                    u64 ok = __shfl_xor_sync(0xffffffffu, nk, s, L);
                    if (ok < nk) nk = ok;
                }
                if (!done) {
                    float b2v; BOXBOUND(r, b2v)
                    if (nk < tkey(__fmaf_rn(b2v, b2v, -EPS))) done = true;
                }
            }
            MERGE(res0, res1, res2, res3, mb3k)
        }
    }
#undef BOXBOUND
#undef MERGE
#undef RUN
#undef PAIR
    if (lane == 0) g_nn[qid] = make_int4(res0, res1, res2, res3);
}

// ---------------------------------------------------------------------------
// K4: FUSED gather + transpose, qid-major, 512 threads/block (16 warps,
// warp = 4 queries) for latency hiding. Rows 256B-coalesced from the
// L2-resident g_vt; 64x64 smem tile (pad 65) -> coalesced out rows.
// Also re-zeroes histogram counters for the next graph replay.
// ---------------------------------------------------------------------------
__global__ void __launch_bounds__(512) k_gather(float* __restrict__ out)
{
    __shared__ float s[64 * 65];

    if (blockIdx.x < 8) {
        int z = blockIdx.x * 512 + threadIdx.x;
        g_cnt[z] = 0; g_qcnt[z] = 0;
    }

    const int q0   = blockIdx.x * 64;
    const int wid  = threadIdx.x >> 5;       // 0..15
    const int lane = threadIdx.x & 31;

    #pragma unroll
    for (int k = 0; k < 4; k++) {
        int ql  = wid * 4 + k;                // 0..63 within tile
        int4 nn = g_nn[q0 + ql];              // broadcast load (same addr/warp)
        const float2* r0 = (const float2*)(g_vt + nn.x * CH);
        const float2* r1 = (const float2*)(g_vt + nn.y * CH);
        const float2* r2 = (const float2*)(g_vt + nn.z * CH);
        const float2* r3 = (const float2*)(g_vt + nn.w * CH);
        float2 a = r0[lane], b = r1[lane], c = r2[lane], d = r3[lane];
        float rx = __fmul_rn(__fadd_rn(__fadd_rn(__fadd_rn(a.x, b.x), c.x), d.x), 0.25f);
        float ry = __fmul_rn(__fadd_rn(__fadd_rn(__fadd_rn(a.y, b.y), c.y), d.y), 0.25f);
        s[ql * 65 + 2 * lane]     = rx;
        s[ql * 65 + 2 * lane + 1] = ry;
    }
    __syncthreads();

    // transposed write: 512 threads cover the 64x64 tile in 8 passes
    const int tq  = threadIdx.x & 63;         // query within tile
    const int tc0 = threadIdx.x >> 6;         // 0..7
    #pragma unroll
    for (int cc = 0; cc < 8; cc++) {
        int c = tc0 + cc * 8;
        out[c * NQ + q0 + tq] = s[tq * 65 + c];
    }
}

extern "C" void kernel_launch(void* const* d_in, const int* in_sizes, int n_in,
                              void* d_out, int out_size)
{
    const float*  values = (const float*)  d_in[0];  // [64, 8192]
    const float2* coords = (const float2*) d_in[1];  // [8192, 2]
    const float2* newc   = (const float2*) d_in[2];  // [24576, 2]
    const float*  shift  = (const float*)  d_in[3];  // [2]
    float* out = (float*)d_out;                      // [64, 32768]

    k_pre    <<<HB, 256>>>(coords, newc, shift);
    k_scatter<<<HB + T_TILES, 256>>>(values, coords, newc, shift);
    k_query  <<<NQ * L / 256, 256>>>();
    k_gather <<<NQ / 64, 512>>>(out);
}

// round 11
// speedup vs baseline: 1.0889x; 1.0889x over previous
#include <cuda_runtime.h>

#define NP     8192
#define NQ     32768
#define CH     64
#define G      64
#define NCELL  (G * G)
#define HCELL  (1.0f / 64.0f)   // exact power of two
#define EPS    1e-5f            // pruning margin >> fp formula error (~2e-6)

#define T_TILES 512             // 32x32 transpose tiles: (64/32)*(8192/32)
#define L      8                // lanes cooperating per query
#define HB     (NQ / 256)       // hist blocks in k_pre
#define QB     (NQ * L / 256)   // query blocks in k_query

typedef unsigned long long u64;
#define KPAD 0xFF8000007FFFFFFFULL   // key(+INF, id=0x7fffffff)

// ---- scratch (__device__ globals: allocation-free rule) ----
// Counters start zero (static init) and are re-zeroed by k_gather each call.
__device__ int    g_cnt[NCELL],  g_off[NCELL + 1];    // points
__device__ int    g_qcnt[NCELL], g_qoff[NCELL + 1];   // queries
__device__ unsigned g_done;      // k_pre tail-block counter (self-resetting)
__device__ int    g_pkey[NP];    // packed cell<<16 | rank  (points)
__device__ int    g_qkey[NQ];    // packed cell<<16 | rank  (queries)
__device__ float4 g_pts[NP];     // cell-sorted points : (x, y, |c|^2, orig-id)
__device__ float4 g_q[NQ];       // cell-sorted queries: (qx, qy, |q|^2, qid)
__device__ int4   g_nn[NQ];      // per ORIGINAL qid: 4 neighbor ORIG ids
__device__ float  g_vt[NP * CH]; // values transposed: vt[orig][c]

static __device__ __forceinline__ int cell_clamped(float px, float py) {
    int cx = (int)(px * (float)G); cx = cx < 0 ? 0 : (cx > G - 1 ? G - 1 : cx);
    int cy = (int)(py * (float)G); cy = cy < 0 ? 0 : (cy > G - 1 ? G - 1 : cy);
    return cy * G + cx;
}

// monotonic (total-order) float -> u32 encode; strict order preserved
static __device__ __forceinline__ unsigned fenc(float d) {
    unsigned u = __float_as_uint(d);
    return u ^ (((unsigned)((int)u >> 31)) | 0x80000000u);
}
// threshold key with id = 0: key < tkey(thr)  <=>  d < thr (strict)
static __device__ __forceinline__ u64 tkey(float thr) {
    return ((u64)fenc(thr)) << 32;
}

// ---------------------------------------------------------------------------
// K1: histogram-with-rank; LAST block also runs the dual scan
// (threadfence + done-counter tail-block pattern, counter self-resets).
// ---------------------------------------------------------------------------
__global__ void __launch_bounds__(256) k_pre(
    const float2* __restrict__ coords,
    const float2* __restrict__ newc,
    const float*  __restrict__ shift)
{
    int i = blockIdx.x * 256 + threadIdx.x;   // 0..NQ-1
    float sx = shift[0], sy = shift[1];
    float2 a = (i < NP) ? coords[i] : newc[i - NP];
    float qx = __fsub_rn(a.x, sx), qy = __fsub_rn(a.y, sy);
    int qc = cell_clamped(qx, qy);
    int qr = atomicAdd(&g_qcnt[qc], 1);
    g_qkey[i] = (qc << 16) | qr;
    if (i < NP) {
        int pc = cell_clamped(a.x, a.y);
        int pr = atomicAdd(&g_cnt[pc], 1);
        g_pkey[i] = (pc << 16) | pr;
    }

    __threadfence();
    __shared__ bool isLast;
    if (threadIdx.x == 0)
        isLast = (atomicAdd(&g_done, 1u) == HB - 1);
    __syncthreads();
    if (!isLast) return;
    if (threadIdx.x == 0) g_done = 0;          // reset for next replay

    // ---- dual exclusive scan of both 4096-cell histograms ----
    __shared__ int pp[256], pq[256];
    int t = threadIdx.x, base = t * 16;
    int lp[16], lq[16], sp = 0, sq = 0;
    #pragma unroll
    for (int k = 0; k < 16; k++) {
        lp[k] = sp; sp += g_cnt[base + k];
        lq[k] = sq; sq += g_qcnt[base + k];
    }
    pp[t] = sp; pq[t] = sq;
    __syncthreads();
    for (int o = 1; o < 256; o <<= 1) {
        int vp = (t >= o) ? pp[t - o] : 0;
        int vq = (t >= o) ? pq[t - o] : 0;
        __syncthreads();
        pp[t] += vp; pq[t] += vq;
        __syncthreads();
    }
    int prep = (t == 0) ? 0 : pp[t - 1];
    int preq = (t == 0) ? 0 : pq[t - 1];
    #pragma unroll
    for (int k = 0; k < 16; k++) {
        g_off[base + k]  = prep + lp[k];
        g_qoff[base + k] = preq + lq[k];
    }
    if (t == 255) { g_off[NCELL] = NP; g_qoff[NCELL] = NQ; }
}

// ---------------------------------------------------------------------------
// K2: atomic-free scatter only (rank captured in k_pre).
// ---------------------------------------------------------------------------
__global__ void __launch_bounds__(256) k_scatter(
    const float2* __restrict__ coords,
    const float2* __restrict__ newc,
    const float*  __restrict__ shift)
{
    int i = blockIdx.x * 256 + threadIdx.x;
    float sx = shift[0], sy = shift[1];
    float2 a = (i < NP) ? coords[i] : newc[i - NP];
    float qx = __fsub_rn(a.x, sx), qy = __fsub_rn(a.y, sy);
    float sq = __fadd_rn(__fmul_rn(qx, qx), __fmul_rn(qy, qy));
    int qk = g_qkey[i];
    g_q[g_qoff[qk >> 16] + (qk & 0xffff)] =
        make_float4(qx, qy, sq, __int_as_float(i));
    if (i < NP) {
        int pk = g_pkey[i];
        float c2 = __fadd_rn(__fmul_rn(a.x, a.x), __fmul_rn(a.y, a.y));
        g_pts[g_off[pk >> 16] + (pk & 0xffff)] =
            make_float4(a.x, a.y, c2, __int_as_float(i));
    }
}

// ---------------------------------------------------------------------------
// K3: exact 4-NN (blocks [0,QB)) + values-transpose (blocks [QB, QB+T_TILES)).
// g_vt is only consumed by k_gather (next launch), so the transpose can ride
// here off the scatter->query critical path. Query: 8 lanes/query, adaptive
// sweep (3x3 -> ring2 -> safety rings); d via the verified fp32 formula,
// (d, orig_id) packed into one sortable u64 key (ordering identical to the
// float lexicographic path; +-0.0 distance excepted, measure-zero).
// ---------------------------------------------------------------------------
__global__ void __launch_bounds__(256) k_query(const float* __restrict__ values)
{
    if (blockIdx.x >= QB) {
        __shared__ float sT[32][33];
        int tb = blockIdx.x - QB;
        int tc = tb & 1;
        int to = tb >> 1;
        int tx = threadIdx.x & 31, ty = threadIdx.x >> 5;
        #pragma unroll
        for (int d = 0; d < 4; d++) {
            int cl = ty + d * 8;
            sT[cl][tx] = values[(tc * 32 + cl) * NP + to * 32 + tx];
        }
        __syncthreads();
        #pragma unroll
        for (int d = 0; d < 4; d++) {
            int ol = ty + d * 8;
            g_vt[(to * 32 + ol) * CH + tc * 32 + tx] = sT[tx][ol];
        }
        return;
    }

    const int gt   = blockIdx.x * 256 + threadIdx.x;
    const int grp  = gt >> 3;          // query index (sorted order)
    const int lane = gt & 7;

    float4 q = g_q[grp];
    const float qx = q.x, qy = q.y, sq = q.z;
    const int qid = __float_as_int(q.w);
    const int cx = (int)floorf(qx * (float)G);   // may be -1 near lower edge
    const int cy = (int)floorf(qy * (float)G);

    u64 k0 = KPAD, k1 = KPAD, k2 = KPAD, k3 = KPAD;

#define PAIR(n) {                                                        \
    float4 p = g_pts[n];                                                 \
    float qc = __fmaf_rn(qy, p.y, __fmul_rn(qx, p.x));                   \
    float tt = __fadd_rn(sq, p.z);                                       \
    float d  = __fmaf_rn(-2.0f, qc, tt);                                 \
    u64 kk = (((u64)fenc(d)) << 32) | (unsigned)__float_as_int(p.w);     \
    if (kk < k3) {                                                       \
        if (kk < k2) {                                                   \
            k3 = k2;                                                     \
            if (kk < k1) {                                               \
                k2 = k1;                                                 \
                if (kk < k0) { k1 = k0; k0 = kk; } else k1 = kk;         \
            } else k2 = kk;                                              \
        } else k3 = kk;                                                  \
    } }

#define RUN(s_, e_) { for (int n = (s_) + lane; n < (e_); n += L) PAIR(n) }

#define MERGE(R0, R1, R2, R3, B3K) {                                    \
    int h = 0;                                                          \
    _Pragma("unroll")                                                   \
    for (int k = 0; k < 4; k++) {                                       \
        u64 ck = (h == 0) ? k0 : (h == 1) ? k1 : (h == 2) ? k2          \
               : (h == 3) ? k3 : KPAD;                                  \
        u64 mk = ck;                                                    \
        _Pragma("unroll")                                               \
        for (int s = 1; s < L; s <<= 1) {                               \
            u64 ok = __shfl_xor_sync(0xffffffffu, mk, s, L);            \
            if (ok < mk) mk = ok;                                       \
        }                                                               \
        if (k == 0) R0 = (int)(mk & 0xffffffffull);                     \
        else if (k == 1) R1 = (int)(mk & 0xffffffffull);                \
        else if (k == 2) R2 = (int)(mk & 0xffffffffull);                \
        else { R3 = (int)(mk & 0xffffffffull); B3K = mk; }              \
        if (ck == mk) h++;                                              \
    } }

#define BOXBOUND(e_, bv_) {                                              \
    float x0 = (float)(cx - (e_)) * HCELL, y0 = (float)(cy - (e_)) * HCELL; \
    float x1 = (float)(cx + (e_) + 1) * HCELL, y1 = (float)(cy + (e_) + 1) * HCELL; \
    bv_ = fminf(fminf(qx - x0, x1 - qx), fminf(qy - y0, y1 - qy)); }

    // ---- phase 1: 3x3 sweep (row-contiguous) ----
    {
        int iy0 = cy - 1 < 0 ? 0 : cy - 1;
        int iy1 = cy + 1 > G - 1 ? G - 1 : cy + 1;
        int ix0 = cx - 1 < 0 ? 0 : cx - 1;
        int ix1 = cx + 1 > G - 1 ? G - 1 : cx + 1;
        for (int iy = iy0; iy <= iy1; iy++)
            RUN(g_off[iy * G + ix0], g_off[iy * G + ix1 + 1])
    }
    int res0, res1, res2, res3;
    u64 mb3k;
    MERGE(res0, res1, res2, res3, mb3k)

    float bb; BOXBOUND(1, bb)
    bool done = (mb3k < tkey(__fmaf_rn(bb, bb, -EPS)));

    if (!__all_sync(0xffffffffu, done)) {
        // ---- phase 2: ring r=2 (guarded per group; no shfl inside) ----
        if (!done) {
            int ix0 = cx - 2 < 0 ? 0 : cx - 2;
            int ix1 = cx + 2 > G - 1 ? G - 1 : cx + 2;
            if (cy - 2 >= 0)
                RUN(g_off[(cy - 2) * G + ix0], g_off[(cy - 2) * G + ix1 + 1])
            if (cy + 2 <= G - 1)
                RUN(g_off[(cy + 2) * G + ix0], g_off[(cy + 2) * G + ix1 + 1])
            int iy0 = cy - 1 < 0 ? 0 : cy - 1;
            int iy1 = cy + 1 > G - 1 ? G - 1 : cy + 1;
            for (int iy = iy0; iy <= iy1; iy++) {
                if (cx - 2 >= 0) {
                    int c = iy * G + cx - 2;
                    RUN(g_off[c], g_off[c + 1])
                }
                if (cx + 2 <= G - 1) {
                    int c = iy * G + cx + 2;
                    RUN(g_off[c], g_off[c + 1])
                }
            }
        }
        MERGE(res0, res1, res2, res3, mb3k)   // uniform re-merge (safe for done)
        BOXBOUND(2, bb)
        done = done || (mb3k < tkey(__fmaf_rn(bb, bb, -EPS)));

        if (!__all_sync(0xffffffffu, done)) {
            // ---- phase 3: safety rings r>=3 ----
            for (int r = 3; r < 96; r++) {
                if (__all_sync(0xffffffffu, done)) break;
                if (!done) {
                    int ylo = cy - r, yhi = cy + r, xlo = cx - r, xhi = cx + r;
                    int ix0 = xlo < 0 ? 0 : xlo;
                    int ix1 = xhi > G - 1 ? G - 1 : xhi;
                    if (ylo >= 0)
                        RUN(g_off[ylo * G + ix0], g_off[ylo * G + ix1 + 1])
                    if (yhi <= G - 1)
                        RUN(g_off[yhi * G + ix0], g_off[yhi * G + ix1 + 1])
                    int iy0 = ylo + 1 < 0 ? 0 : ylo + 1;
                    int iy1 = yhi - 1 > G - 1 ? G - 1 : yhi - 1;
                    for (int iy = iy0; iy <= iy1; iy++) {
                        if (xlo >= 0) {
                            int c = iy * G + xlo;
                            RUN(g_off[c], g_off[c + 1])
                        }
                        if (xhi <= G - 1) {
                            int c = iy * G + xhi;
                            RUN(g_off[c], g_off[c + 1])
                        }
                    }
                }
                u64 nk = k3;   // conservative: min over lanes of lane 4th key
                #pragma unroll
                for (int s = 1; s < L; s <<= 1) {
                    u64 ok = __shfl_xor_sync(0xffffffffu, nk, s, L);
                    if (ok < nk) nk = ok;
                }
                if (!done) {
                    float b2v; BOXBOUND(r, b2v)
                    if (nk < tkey(__fmaf_rn(b2v, b2v, -EPS))) done = true;
                }
            }
            MERGE(res0, res1, res2, res3, mb3k)
        }
    }
#undef BOXBOUND
#undef MERGE
#undef RUN
#undef PAIR
    if (lane == 0) g_nn[qid] = make_int4(res0, res1, res2, res3);
}

// ---------------------------------------------------------------------------
// K4: FUSED gather + transpose, qid-major, LDG.128 path. Warp handles 2
// queries at a time (half-warp per query, lane = float4 = 4 channels, so one
// LDG.128 instruction fetches TWO 256B rows). All 8 row-loads of both
// query-pairs are front-batched before any arithmetic -> 8x16B in flight
// per lane. 64x64 smem tile (pad 65) -> coalesced out rows. Also re-zeroes
// histogram counters for the next graph replay.
// ---------------------------------------------------------------------------
__global__ void __launch_bounds__(512) k_gather(float* __restrict__ out)
{
    __shared__ float s[64 * 65];

    if (blockIdx.x < 8) {
        int z = blockIdx.x * 512 + threadIdx.x;
        g_cnt[z] = 0; g_qcnt[z] = 0;
    }

    const int q0   = blockIdx.x * 64;
    const int wid  = threadIdx.x >> 5;       // 0..15
    const int lane = threadIdx.x & 31;
    const int half = lane >> 4;               // 0/1: which query of the pair
    const int hl   = lane & 15;               // float4 slot within the row

    // queries handled by this lane: wid*4 + {0,1} pair-slot + half
    const int qlA = wid * 4 + half;           // pair 0
    const int qlB = wid * 4 + 2 + half;       // pair 1

    int4 nnA = g_nn[q0 + qlA];
    int4 nnB = g_nn[q0 + qlB];

    // front-batch all 8 independent 16B loads
    float4 a0 = ((const float4*)(g_vt + nnA.x * CH))[hl];
    float4 a1 = ((const float4*)(g_vt + nnA.y * CH))[hl];
    float4 a2 = ((const float4*)(g_vt + nnA.z * CH))[hl];
    float4 a3 = ((const float4*)(g_vt + nnA.w * CH))[hl];
    float4 b0 = ((const float4*)(g_vt + nnB.x * CH))[hl];
    float4 b1 = ((const float4*)(g_vt + nnB.y * CH))[hl];
    float4 b2 = ((const float4*)(g_vt + nnB.z * CH))[hl];
    float4 b3 = ((const float4*)(g_vt + nnB.w * CH))[hl];

#define SUM4(r_, p_, q_, s_, t_) \
    __fmul_rn(__fadd_rn(__fadd_rn(__fadd_rn(p_, q_), s_), t_), 0.25f)

    {
        float* dst = s + qlA * 65 + 4 * hl;
        dst[0] = SUM4(, a0.x, a1.x, a2.x, a3.x);
        dst[1] = SUM4(, a0.y, a1.y, a2.y, a3.y);
        dst[2] = SUM4(, a0.z, a1.z, a2.z, a3.z);
        dst[3] = SUM4(, a0.w, a1.w, a2.w, a3.w);
    }
    {
        float* dst = s + qlB * 65 + 4 * hl;
        dst[0] = SUM4(, b0.x, b1.x, b2.x, b3.x);
        dst[1] = SUM4(, b0.y, b1.y, b2.y, b3.y);
        dst[2] = SUM4(, b0.z, b1.z, b2.z, b3.z);
        dst[3] = SUM4(, b0.w, b1.w, b2.w, b3.w);
    }
#undef SUM4
    __syncthreads();

    // transposed write: 512 threads cover the 64x64 tile in 8 passes
    const int tq  = threadIdx.x & 63;         // query within tile
    const int tc0 = threadIdx.x >> 6;         // 0..7
    #pragma unroll
    for (int cc = 0; cc < 8; cc++) {
        int c = tc0 + cc * 8;
        out[c * NQ + q0 + tq] = s[tq * 65 + c];
    }
}

extern "C" void kernel_launch(void* const* d_in, const int* in_sizes, int n_in,
                              void* d_out, int out_size)
{
    const float*  values = (const float*)  d_in[0];  // [64, 8192]
    const float2* coords = (const float2*) d_in[1];  // [8192, 2]
    const float2* newc   = (const float2*) d_in[2];  // [24576, 2]
    const float*  shift  = (const float*)  d_in[3];  // [2]
    float* out = (float*)d_out;                      // [64, 32768]

    k_pre    <<<HB, 256>>>(coords, newc, shift);
    k_scatter<<<HB, 256>>>(coords, newc, shift);
    k_query  <<<QB + T_TILES, 256>>>(values);
    k_gather <<<NQ / 64, 512>>>(out);
}